// round 2
// baseline (speedup 1.0000x reference)
#include <cuda_runtime.h>

#define N_NODES 50000
#define H 64
#define HC 32          // H/2 complex pairs
#define HEADS 4
#define M_PATHS 2
#define E_EDGES 250000
#define P_LEN 3
#define FH 128
#define D 256          // heads * H
#define FH2 256        // 2 * FH

// ---------------- scratch (device globals; no allocations allowed) ----------
__device__ float g_eft[E_EDGES * H];          // 64 MB  (per-path, reused)
__device__ float g_ex[E_EDGES * HEADS];       // 4 MB
__device__ float g_den[N_NODES * HEADS];      // 0.8 MB
__device__ float g_z[M_PATHS * N_NODES * D];  // 102.4 MB (hsum -> celu(z))
__device__ float g_fw1T[D * FH2];             // fw1 transposed [k][j] 256x256
__device__ float g_fw2T[FH2 * FH];            // fw2 transposed [k][j] 256x128
__device__ float g_wsum[2];
__device__ float g_beta[2];

__device__ __forceinline__ float celu3f(float x) {
    return x > 0.0f ? x : 3.0f * expm1f(x * (1.0f / 3.0f));
}

// ---------------- prep: transpose MLP weights, zero wsum --------------------
__global__ void prep_kernel(const float* __restrict__ fw1,
                            const float* __restrict__ fw2) {
    int idx = blockIdx.x * blockDim.x + threadIdx.x;
    if (idx < FH2 * D) {
        int j = idx / D;            // output row of fw1
        int k = idx - j * D;        // input col
        g_fw1T[k * FH2 + j] = fw1[idx];
    } else if (idx < FH2 * D + FH * FH2) {
        int i2 = idx - FH2 * D;
        int j = i2 / FH2;
        int k = i2 - j * FH2;
        g_fw2T[k * FH + j] = fw2[i2];
    }
    if (idx == 0) { g_wsum[0] = 0.0f; g_wsum[1] = 0.0f; }
}

__global__ void zero_z_kernel() {
    int i = blockIdx.x * blockDim.x + threadIdx.x;
    int n4 = M_PATHS * N_NODES * D / 4;
    if (i < n4) ((float4*)g_z)[i] = make_float4(0.f, 0.f, 0.f, 0.f);
}

__global__ void zero_den_kernel() {
    int i = blockIdx.x * blockDim.x + threadIdx.x;
    if (i < N_NODES * HEADS) g_den[i] = 0.0f;
}

// ---------------- edge pass 1: gather+rotate+eft+logits+den -----------------
// one warp per edge; lane l owns complex pair l (channels 2l, 2l+1)
__global__ void __launch_bounds__(256) pass1_kernel(
    const float* __restrict__ features, const float* __restrict__ r_vec,
    const float* __restrict__ attn1_w, const float* __restrict__ attn2,
    const int* __restrict__ inst_m, int m) {
    int warp = threadIdx.x >> 5, lane = threadIdx.x & 31;
    int e = blockIdx.x * 8 + warp;
    if (e >= E_EDGES) return;

    // rotation factors: fr[2]=1, fr[1]=rv[2m+1], fr[0]=rv[2m]*rv[2m+1]
    const float2* rv = (const float2*)r_vec;
    float2 ra = rv[(2 * m) * HC + lane];
    float2 rb = rv[(2 * m + 1) * HC + lane];
    float ia = rsqrtf(ra.x * ra.x + ra.y * ra.y);
    float ib = rsqrtf(rb.x * rb.x + rb.y * rb.y);
    ra.x *= ia; ra.y *= ia; rb.x *= ib; rb.y *= ib;
    float fr0x = rb.x * ra.x - rb.y * ra.y;
    float fr0y = rb.x * ra.y + rb.y * ra.x;

    const int* ip = inst_m + e * 3;
    int i0 = ip[0], i1 = ip[1], i2 = ip[2];
    const float2* F = (const float2*)features;
    float2 f0 = F[i0 * HC + lane];
    float2 f1 = F[i1 * HC + lane];
    float2 f2 = F[i2 * HC + lane];

    // me = mean over p of cmul(edata_p, fr_p)
    float mre = (f0.x * fr0x - f0.y * fr0y) + (f1.x * rb.x - f1.y * rb.y) + f2.x;
    float mim = (f0.x * fr0y + f0.y * fr0x) + (f1.x * rb.y + f1.y * rb.x) + f2.y;
    mre *= (1.0f / 3.0f); mim *= (1.0f / 3.0f);

    float se0 = celu3f(mre) * (1.0f / (1.0f + expf(-mre)));
    float se1 = celu3f(mim) * (1.0f / (1.0f + expf(-mim)));
    float ef0 = celu3f(se0), ef1 = celu3f(se1);

    ((float2*)(g_eft + e * H))[lane] = make_float2(ef0, ef1);

    // a1 = celu3(features[seg] @ attn1_w.T), a2 = eft @ attn2.T
    float r[8];
    const float2* W1 = (const float2*)attn1_w;
    const float2* W2 = (const float2*)attn2;
#pragma unroll
    for (int k = 0; k < 4; k++) {
        float2 w1 = W1[k * HC + lane];
        float2 w2 = W2[k * HC + lane];
        r[k]     = w1.x * f0.x + w1.y * f0.y;
        r[4 + k] = w2.x * ef0  + w2.y * ef1;
    }
#pragma unroll
    for (int off = 16; off; off >>= 1)
#pragma unroll
        for (int i = 0; i < 8; i++)
            r[i] += __shfl_xor_sync(0xffffffffu, r[i], off);

    if (lane == 0) {
#pragma unroll
        for (int k = 0; k < 4; k++) {
            float a = celu3f(celu3f(r[k]) + r[4 + k]);
            float ex = expf(a);             // no max-sub: |a| bounded, exp safe
            g_ex[e * 4 + k] = ex;
            atomicAdd(&g_den[i0 * 4 + k], ex);
        }
    }
}

// ---------------- edge pass 2: scatter attn*eft into node hsum --------------
// lane l: head k = l>>3, channel block h8 = (l&7)*8 -> two red.v4 per lane
__global__ void __launch_bounds__(256) pass2_kernel(
    const int* __restrict__ inst_m, int m) {
    int warp = threadIdx.x >> 5, lane = threadIdx.x & 31;
    int e = blockIdx.x * 8 + warp;
    if (e >= E_EDGES) return;
    int seg = inst_m[e * 3];
    int k = lane >> 3;
    int h8 = (lane & 7) * 8;
    float ex = g_ex[e * 4 + k];
    float dn = g_den[seg * 4 + k];
    float at = ex / dn;
    const float4* ef4 = (const float4*)(g_eft + e * H + h8);
    float4 ea = ef4[0], eb = ef4[1];
    float* base = g_z + ((size_t)m * N_NODES + seg) * D + k * H + h8;
    asm volatile("red.global.add.v4.f32 [%0], {%1,%2,%3,%4};" ::
                 "l"(base), "f"(at * ea.x), "f"(at * ea.y),
                 "f"(at * ea.z), "f"(at * ea.w) : "memory");
    asm volatile("red.global.add.v4.f32 [%0], {%1,%2,%3,%4};" ::
                 "l"(base + 4), "f"(at * eb.x), "f"(at * eb.y),
                 "f"(at * eb.z), "f"(at * eb.w) : "memory");
}

// ---------------- z = celu3(hsum), in place ---------------------------------
__global__ void celu_z_kernel() {
    int i = blockIdx.x * blockDim.x + threadIdx.x;
    if (i < M_PATHS * N_NODES * D) g_z[i] = celu3f(g_z[i]);
}

// ---------------- MLP: 8 node-path rows per block, fp32 ---------------------
__global__ void __launch_bounds__(256) mlp_kernel(
    const float* __restrict__ fb1, const float* __restrict__ fb2,
    const float* __restrict__ fw3) {
    __shared__ float zt[D * 8];     // [k][t]
    __shared__ float ps[FH2 * 8];   // phase-2 partials [j][t]
    __shared__ float wsums[4][8];
    int j = threadIdx.x;
    int r0 = blockIdx.x * 8;

#pragma unroll
    for (int t = 0; t < 8; t++)
        zt[j * 8 + t] = g_z[(size_t)(r0 + t) * D + j];
    __syncthreads();

    // layer 1: t1 = celu3(fw1 @ z + fb1)
    float acc[8];
    float b1 = fb1[j];
#pragma unroll
    for (int t = 0; t < 8; t++) acc[t] = b1;
    for (int k = 0; k < D; k++) {
        float wv = g_fw1T[k * FH2 + j];
        float4 za = *(const float4*)&zt[k * 8];
        float4 zb = *(const float4*)&zt[k * 8 + 4];
        acc[0] += wv * za.x; acc[1] += wv * za.y;
        acc[2] += wv * za.z; acc[3] += wv * za.w;
        acc[4] += wv * zb.x; acc[5] += wv * zb.y;
        acc[6] += wv * zb.z; acc[7] += wv * zb.w;
    }
    __syncthreads();
#pragma unroll
    for (int t = 0; t < 8; t++) zt[j * 8 + t] = celu3f(acc[t]);
    __syncthreads();

    // layer 2 (split-k over thread halves): t2 = celu3(fw2 @ t1 + fb2)
    int jj = j & 127, half = j >> 7;
    float acc2[8];
    float b2 = (half == 0) ? fb2[jj] : 0.0f;
#pragma unroll
    for (int t = 0; t < 8; t++) acc2[t] = b2;
    for (int kk = 0; kk < 128; kk++) {
        int k = half * 128 + kk;
        float wv = g_fw2T[k * FH + jj];
        float4 za = *(const float4*)&zt[k * 8];
        float4 zb = *(const float4*)&zt[k * 8 + 4];
        acc2[0] += wv * za.x; acc2[1] += wv * za.y;
        acc2[2] += wv * za.z; acc2[3] += wv * za.w;
        acc2[4] += wv * zb.x; acc2[5] += wv * zb.y;
        acc2[6] += wv * zb.z; acc2[7] += wv * zb.w;
    }
#pragma unroll
    for (int t = 0; t < 8; t++) ps[j * 8 + t] = acc2[t];
    __syncthreads();

    // s = fw3 . t2, reduce over j
    float contrib[8];
    if (j < 128) {
        float w3 = fw3[j];
#pragma unroll
        for (int t = 0; t < 8; t++) {
            float t2 = celu3f(ps[j * 8 + t] + ps[(j + 128) * 8 + t]);
            contrib[t] = w3 * t2;
        }
    } else {
#pragma unroll
        for (int t = 0; t < 8; t++) contrib[t] = 0.0f;
    }
#pragma unroll
    for (int off = 16; off; off >>= 1)
#pragma unroll
        for (int t = 0; t < 8; t++)
            contrib[t] += __shfl_xor_sync(0xffffffffu, contrib[t], off);
    int warp = j >> 5, lane = j & 31;
    if (lane == 0 && warp < 4) {
#pragma unroll
        for (int t = 0; t < 8; t++) wsums[warp][t] = contrib[t];
    }
    __syncthreads();
    if (j == 0) {
        float s = 0.0f;
        for (int w = 0; w < 4; w++)
            for (int t = 0; t < 8; t++) s += wsums[w][t];
        int mm = (r0 >= N_NODES) ? 1 : 0;  // block never straddles m (8 | 50000)
        atomicAdd(&g_wsum[mm], s);
    }
}

__global__ void beta_kernel() {
    float w0 = g_wsum[0] * (1.0f / (float)N_NODES);
    float w1 = g_wsum[1] * (1.0f / (float)N_NODES);
    float mx = fmaxf(w0, w1);
    float e0 = expf(w0 - mx), e1 = expf(w1 - mx);
    float inv = 1.0f / (e0 + e1);
    g_beta[0] = e0 * inv;
    g_beta[1] = e1 * inv;
}

__global__ void combine_kernel(float* __restrict__ out) {
    int i = blockIdx.x * blockDim.x + threadIdx.x;
    int n4 = N_NODES * D / 4;
    if (i < n4) {
        float b0 = g_beta[0], b1 = g_beta[1];
        float4 a = ((const float4*)g_z)[i];
        float4 c = ((const float4*)(g_z + (size_t)N_NODES * D))[i];
        float4 o;
        o.x = b0 * a.x + b1 * c.x;
        o.y = b0 * a.y + b1 * c.y;
        o.z = b0 * a.z + b1 * c.z;
        o.w = b0 * a.w + b1 * c.w;
        ((float4*)out)[i] = o;
    }
}

extern "C" void kernel_launch(void* const* d_in, const int* in_sizes, int n_in,
                              void* d_out, int out_size) {
    const float* features = (const float*)d_in[0];
    const float* r_vec    = (const float*)d_in[1];
    const float* attn1_w  = (const float*)d_in[2];
    const float* attn2    = (const float*)d_in[3];
    const float* fw1      = (const float*)d_in[4];
    const float* fb1      = (const float*)d_in[5];
    const float* fw2      = (const float*)d_in[6];
    const float* fb2      = (const float*)d_in[7];
    const float* fw3      = (const float*)d_in[8];
    const int*   inst     = (const int*)d_in[9];
    float* out = (float*)d_out;

    prep_kernel<<<(FH2 * D + FH * FH2 + 255) / 256, 256>>>(fw1, fw2);
    zero_z_kernel<<<(M_PATHS * N_NODES * D / 4 + 255) / 256, 256>>>();

    for (int m = 0; m < M_PATHS; m++) {
        zero_den_kernel<<<(N_NODES * HEADS + 255) / 256, 256>>>();
        const int* inst_m = inst + m * E_EDGES * P_LEN;
        pass1_kernel<<<E_EDGES / 8, 256>>>(features, r_vec, attn1_w, attn2,
                                           inst_m, m);
        pass2_kernel<<<E_EDGES / 8, 256>>>(inst_m, m);
    }

    celu_z_kernel<<<(M_PATHS * N_NODES * D + 255) / 256, 256>>>();
    mlp_kernel<<<(M_PATHS * N_NODES) / 8, 256>>>(fb1, fb2, fw3);
    beta_kernel<<<1, 1>>>();
    combine_kernel<<<(N_NODES * D / 4 + 255) / 256, 256>>>(out);
}

// round 3
// speedup vs baseline: 1.1880x; 1.1880x over previous
#include <cuda_runtime.h>

#define N_NODES 50000
#define H 64
#define HC 32          // H/2 complex pairs
#define HEADS 4
#define M_PATHS 2
#define E_EDGES 250000
#define P_LEN 3
#define FH 128
#define D 256          // heads * H
#define FH2 256        // 2 * FH
#define MT 32          // mlp rows per block

// ---------------- scratch (device globals; no allocations allowed) ----------
__device__ float g_eft[E_EDGES * H];          // 64 MB  (per-path, reused)
__device__ float g_ex[E_EDGES * HEADS];       // 4 MB
__device__ float g_den[N_NODES * HEADS];      // 0.8 MB
__device__ float g_a1[N_NODES * HEADS];       // celu3(features @ attn1_w.T)
__device__ float g_z[M_PATHS * N_NODES * D];  // 102.4 MB (raw hsum)
__device__ float g_fw1T[D * FH2];             // fw1 transposed [k][j] 256x256
__device__ float g_fw2T[FH2 * FH];            // fw2 transposed [k][j] 256x128
__device__ float g_wsum[2];
__device__ float g_beta[2];

__device__ __forceinline__ float celu3f(float x) {
    return x > 0.0f ? x : 3.0f * expm1f(x * (1.0f / 3.0f));
}

#define PACK_F32X2(out, lo, hi) \
    asm("mov.b64 %0, {%1, %2};" : "=l"(out) : "f"(lo), "f"(hi))
#define UNPACK_F32X2(lo, hi, in) \
    asm("mov.b64 {%0, %1}, %2;" : "=f"(lo), "=f"(hi) : "l"(in))
#define FMA_F32X2(d, a, b, c) \
    asm("fma.rn.f32x2 %0, %1, %2, %3;" : "=l"(d) : "l"(a), "l"(b), "l"(c))

// ---------------- prep: transpose MLP weights, zero wsum --------------------
__global__ void prep_kernel(const float* __restrict__ fw1,
                            const float* __restrict__ fw2) {
    int idx = blockIdx.x * blockDim.x + threadIdx.x;
    if (idx < FH2 * D) {
        int j = idx / D;
        int k = idx - j * D;
        g_fw1T[k * FH2 + j] = fw1[idx];
    } else if (idx < FH2 * D + FH * FH2) {
        int i2 = idx - FH2 * D;
        int j = i2 / FH2;
        int k = i2 - j * FH2;
        g_fw2T[k * FH + j] = fw2[i2];
    }
    if (idx == 0) { g_wsum[0] = 0.0f; g_wsum[1] = 0.0f; }
}

__global__ void zero_z_kernel() {
    int i = blockIdx.x * blockDim.x + threadIdx.x;
    int n4 = M_PATHS * N_NODES * D / 4;
    if (i < n4) ((float4*)g_z)[i] = make_float4(0.f, 0.f, 0.f, 0.f);
}

__global__ void zero_den_kernel() {
    int i = blockIdx.x * blockDim.x + threadIdx.x;
    if (i < N_NODES * HEADS) g_den[i] = 0.0f;
}

// ---------------- per-node a1 = celu3(features @ attn1_w.T) -----------------
__global__ void __launch_bounds__(256) a1_kernel(
    const float* __restrict__ features, const float* __restrict__ attn1_w) {
    int warp = threadIdx.x >> 5, lane = threadIdx.x & 31;
    int node = blockIdx.x * 8 + warp;
    if (node >= N_NODES) return;
    float2 f = ((const float2*)features)[node * HC + lane];
    const float2* W1 = (const float2*)attn1_w;
    float r[4];
#pragma unroll
    for (int k = 0; k < 4; k++) {
        float2 w = W1[k * HC + lane];
        r[k] = w.x * f.x + w.y * f.y;
    }
#pragma unroll
    for (int off = 16; off; off >>= 1)
#pragma unroll
        for (int k = 0; k < 4; k++)
            r[k] += __shfl_xor_sync(0xffffffffu, r[k], off);
    if (lane == 0) {
#pragma unroll
        for (int k = 0; k < 4; k++) g_a1[node * 4 + k] = celu3f(r[k]);
    }
}

// ---------------- edge pass 1: gather+rotate+eft+logits+den -----------------
__global__ void __launch_bounds__(256) pass1_kernel(
    const float* __restrict__ features, const float* __restrict__ r_vec,
    const float* __restrict__ attn2, const int* __restrict__ inst_m, int m) {
    int warp = threadIdx.x >> 5, lane = threadIdx.x & 31;
    int e = blockIdx.x * 8 + warp;
    if (e >= E_EDGES) return;

    const float2* rv = (const float2*)r_vec;
    float2 ra = rv[(2 * m) * HC + lane];
    float2 rb = rv[(2 * m + 1) * HC + lane];
    float ia = rsqrtf(ra.x * ra.x + ra.y * ra.y);
    float ib = rsqrtf(rb.x * rb.x + rb.y * rb.y);
    ra.x *= ia; ra.y *= ia; rb.x *= ib; rb.y *= ib;
    float fr0x = rb.x * ra.x - rb.y * ra.y;
    float fr0y = rb.x * ra.y + rb.y * ra.x;

    const int* ip = inst_m + e * 3;
    int i0 = ip[0], i1 = ip[1], i2 = ip[2];
    const float2* F = (const float2*)features;
    float2 f0 = F[i0 * HC + lane];
    float2 f1 = F[i1 * HC + lane];
    float2 f2 = F[i2 * HC + lane];

    float mre = (f0.x * fr0x - f0.y * fr0y) + (f1.x * rb.x - f1.y * rb.y) + f2.x;
    float mim = (f0.x * fr0y + f0.y * fr0x) + (f1.x * rb.y + f1.y * rb.x) + f2.y;
    mre *= (1.0f / 3.0f); mim *= (1.0f / 3.0f);

    float se0 = celu3f(mre) * (1.0f / (1.0f + expf(-mre)));
    float se1 = celu3f(mim) * (1.0f / (1.0f + expf(-mim)));
    float ef0 = celu3f(se0), ef1 = celu3f(se1);

    ((float2*)(g_eft + e * H))[lane] = make_float2(ef0, ef1);

    // a2 = eft @ attn2.T (4 heads)
    float r[4];
    const float2* W2 = (const float2*)attn2;
#pragma unroll
    for (int k = 0; k < 4; k++) {
        float2 w2 = W2[k * HC + lane];
        r[k] = w2.x * ef0 + w2.y * ef1;
    }
#pragma unroll
    for (int off = 16; off; off >>= 1)
#pragma unroll
        for (int k = 0; k < 4; k++)
            r[k] += __shfl_xor_sync(0xffffffffu, r[k], off);

    if (lane == 0) {
#pragma unroll
        for (int k = 0; k < 4; k++) {
            float a = celu3f(g_a1[i0 * 4 + k] + r[k]);
            float ex = expf(a);   // logits bounded; no max-sub needed
            g_ex[e * 4 + k] = ex;
            atomicAdd(&g_den[i0 * 4 + k], ex);
        }
    }
}

// ---------------- edge pass 2: scatter attn*eft into node hsum --------------
__global__ void __launch_bounds__(256) pass2_kernel(
    const int* __restrict__ inst_m, int m) {
    int warp = threadIdx.x >> 5, lane = threadIdx.x & 31;
    int e = blockIdx.x * 8 + warp;
    if (e >= E_EDGES) return;
    int seg = inst_m[e * 3];
    int k = lane >> 3;
    int h8 = (lane & 7) * 8;
    float ex = g_ex[e * 4 + k];
    float dn = g_den[seg * 4 + k];
    float at = ex / dn;
    const float4* ef4 = (const float4*)(g_eft + e * H + h8);
    float4 ea = ef4[0], eb = ef4[1];
    float* base = g_z + ((size_t)m * N_NODES + seg) * D + k * H + h8;
    asm volatile("red.global.add.v4.f32 [%0], {%1,%2,%3,%4};" ::
                 "l"(base), "f"(at * ea.x), "f"(at * ea.y),
                 "f"(at * ea.z), "f"(at * ea.w) : "memory");
    asm volatile("red.global.add.v4.f32 [%0], {%1,%2,%3,%4};" ::
                 "l"(base + 4), "f"(at * eb.x), "f"(at * eb.y),
                 "f"(at * eb.z), "f"(at * eb.w) : "memory");
}

// ---------------- MLP: 32 rows/block, packed f32x2 FFMA ---------------------
// z celu applied on load; rows t and t+16 packed into one b64 lane pair.
__global__ void __launch_bounds__(256, 2) mlp_kernel(
    const float* __restrict__ fb1, const float* __restrict__ fb2,
    const float* __restrict__ fw3) {
    // zs: [256 rows][18 ull] (16 used + 1 ull pad to kill write conflicts,
    // row stride 144B keeps 16B alignment for LDS.128)
    __shared__ unsigned long long zs[256 * 18];
    float* zsf = (float*)zs;
    int j = threadIdx.x;
    int r0 = blockIdx.x * MT;

    // ---- stage z (celu applied) ----
#pragma unroll
    for (int t = 0; t < MT; t++) {
        float v = celu3f(g_z[(size_t)(r0 + t) * D + j]);
        zsf[j * 36 + (t & 15) * 2 + (t >> 4)] = v;
    }
    __syncthreads();

    // ---- layer 1: t1 = celu3(fw1 @ z + fb1), 256 outputs ----
    unsigned long long acc[16];
    {
        float b1 = fb1[j];
        unsigned long long bp; PACK_F32X2(bp, b1, b1);
#pragma unroll
        for (int i = 0; i < 16; i++) acc[i] = bp;
    }
    for (int k = 0; k < D; k++) {
        float wv = g_fw1T[k * FH2 + j];
        unsigned long long wp; PACK_F32X2(wp, wv, wv);
        const ulonglong2* zp = (const ulonglong2*)(zs + k * 18);
#pragma unroll
        for (int q = 0; q < 8; q++) {
            ulonglong2 zv = zp[q];
            FMA_F32X2(acc[2 * q],     wp, zv.x, acc[2 * q]);
            FMA_F32X2(acc[2 * q + 1], wp, zv.y, acc[2 * q + 1]);
        }
    }
    __syncthreads();
#pragma unroll
    for (int i = 0; i < 16; i++) {
        float lo, hi; UNPACK_F32X2(lo, hi, acc[i]);
        zsf[j * 36 + i * 2]     = celu3f(lo);
        zsf[j * 36 + i * 2 + 1] = celu3f(hi);
    }
    __syncthreads();

    // ---- layer 2 (split-k halves): t2 = celu3(fw2 @ t1 + fb2), 128 out ----
    int jj = j & 127, half = j >> 7;
    unsigned long long acc2[16];
    {
        float b2 = half ? 0.0f : fb2[jj];
        unsigned long long bp; PACK_F32X2(bp, b2, b2);
#pragma unroll
        for (int i = 0; i < 16; i++) acc2[i] = bp;
    }
    for (int kk = 0; kk < 128; kk++) {
        int k = half * 128 + kk;
        float wv = g_fw2T[k * FH + jj];
        unsigned long long wp; PACK_F32X2(wp, wv, wv);
        const ulonglong2* zp = (const ulonglong2*)(zs + k * 18);
#pragma unroll
        for (int q = 0; q < 8; q++) {
            ulonglong2 zv = zp[q];
            FMA_F32X2(acc2[2 * q],     wp, zv.x, acc2[2 * q]);
            FMA_F32X2(acc2[2 * q + 1], wp, zv.y, acc2[2 * q + 1]);
        }
    }
    __syncthreads();

    // ---- partials into psm [256][33] floats (aliases zs) ----
    float* psm = zsf;
#pragma unroll
    for (int i = 0; i < 16; i++) {
        float lo, hi; UNPACK_F32X2(lo, hi, acc2[i]);
        psm[j * 33 + i]      = lo;   // row i
        psm[j * 33 + 16 + i] = hi;   // row i+16
    }
    __syncthreads();

    // ---- layer 3: combine halves, celu, * fw3 ----
    if (j < 128) {
        float w3 = fw3[j];
#pragma unroll 8
        for (int t = 0; t < MT; t++) {
            float t2 = celu3f(psm[j * 33 + t] + psm[(j + 128) * 33 + t]);
            psm[j * 33 + t] = w3 * t2;   // row j slot read only by this thread
        }
    }
    __syncthreads();

    // ---- column sums by warp 0, split by m, two atomics ----
    if (j < 32) {
        float s = 0.0f;
#pragma unroll 8
        for (int q = 0; q < 128; q++) s += psm[q * 33 + j];
        int row = r0 + j;
        float v0 = (row < N_NODES) ? s : 0.0f;
        float v1 = (row < N_NODES) ? 0.0f : s;
#pragma unroll
        for (int off = 16; off; off >>= 1) {
            v0 += __shfl_xor_sync(0xffffffffu, v0, off);
            v1 += __shfl_xor_sync(0xffffffffu, v1, off);
        }
        if (j == 0) {
            atomicAdd(&g_wsum[0], v0);
            atomicAdd(&g_wsum[1], v1);
        }
    }
}

__global__ void beta_kernel() {
    float w0 = g_wsum[0] * (1.0f / (float)N_NODES);
    float w1 = g_wsum[1] * (1.0f / (float)N_NODES);
    float mx = fmaxf(w0, w1);
    float e0 = expf(w0 - mx), e1 = expf(w1 - mx);
    float inv = 1.0f / (e0 + e1);
    g_beta[0] = e0 * inv;
    g_beta[1] = e1 * inv;
}

__global__ void combine_kernel(float* __restrict__ out) {
    int i = blockIdx.x * blockDim.x + threadIdx.x;
    int n4 = N_NODES * D / 4;
    if (i < n4) {
        float b0 = g_beta[0], b1 = g_beta[1];
        float4 a = ((const float4*)g_z)[i];
        float4 c = ((const float4*)(g_z + (size_t)N_NODES * D))[i];
        float4 o;
        o.x = b0 * celu3f(a.x) + b1 * celu3f(c.x);
        o.y = b0 * celu3f(a.y) + b1 * celu3f(c.y);
        o.z = b0 * celu3f(a.z) + b1 * celu3f(c.z);
        o.w = b0 * celu3f(a.w) + b1 * celu3f(c.w);
        ((float4*)out)[i] = o;
    }
}

extern "C" void kernel_launch(void* const* d_in, const int* in_sizes, int n_in,
                              void* d_out, int out_size) {
    const float* features = (const float*)d_in[0];
    const float* r_vec    = (const float*)d_in[1];
    const float* attn1_w  = (const float*)d_in[2];
    const float* attn2    = (const float*)d_in[3];
    const float* fw1      = (const float*)d_in[4];
    const float* fb1      = (const float*)d_in[5];
    const float* fw2      = (const float*)d_in[6];
    const float* fb2      = (const float*)d_in[7];
    const float* fw3      = (const float*)d_in[8];
    const int*   inst     = (const int*)d_in[9];
    float* out = (float*)d_out;

    prep_kernel<<<(FH2 * D + FH * FH2 + 255) / 256, 256>>>(fw1, fw2);
    zero_z_kernel<<<(M_PATHS * N_NODES * D / 4 + 255) / 256, 256>>>();
    a1_kernel<<<(N_NODES + 7) / 8, 256>>>(features, attn1_w);

    for (int m = 0; m < M_PATHS; m++) {
        zero_den_kernel<<<(N_NODES * HEADS + 255) / 256, 256>>>();
        const int* inst_m = inst + m * E_EDGES * P_LEN;
        pass1_kernel<<<E_EDGES / 8, 256>>>(features, r_vec, attn2, inst_m, m);
        pass2_kernel<<<E_EDGES / 8, 256>>>(inst_m, m);
    }

    mlp_kernel<<<(M_PATHS * N_NODES) / MT, 256>>>(fb1, fb2, fw3);
    beta_kernel<<<1, 1>>>();
    combine_kernel<<<(N_NODES * D / 4 + 255) / 256, 256>>>(out);
}

// round 5
// speedup vs baseline: 1.2709x; 1.0698x over previous
#include <cuda_runtime.h>

#define N_NODES 50000
#define H 64
#define HC 32
#define HEADS 4
#define M_PATHS 2
#define E_EDGES 250000
#define P_LEN 3
#define FH 128
#define D 256
#define R_TOT (M_PATHS * N_NODES)      // 100000 rows
#define TILE 32
#define NTILES (R_TOT / TILE)          // 3125
#define ZST 260                         // smem row stride (floats), conflict-free
#define GRID_MLP 148
#define SMEM_MLP ((128 + TILE) * ZST * 4)   // 166400 B

// ---------------- scratch (device globals) ----------------------------------
__device__ float g_den[R_TOT * HEADS];          // per (path,node,head); -> recip
__device__ float g_a1[N_NODES * HEADS];         // celu3(features @ attn1_w.T)
__device__ float g_z[(size_t)R_TOT * D];        // raw  sum(ex*eft)  102.4 MB
__device__ float g_t1[(size_t)R_TOT * D];       // MLP layer-1 output 102.4 MB
__device__ float g_wsum[2];
__device__ float g_beta[2];

__device__ __forceinline__ float celu3f(float x) {
    return x > 0.0f ? x : 3.0f * expm1f(x * (1.0f / 3.0f));
}
__device__ __forceinline__ unsigned tf32r(float x) {
    unsigned r; asm("cvt.rna.tf32.f32 %0, %1;" : "=r"(r) : "f"(x)); return r;
}
__device__ __forceinline__ void mma_tf32(float* c, const unsigned* a,
                                         const unsigned* b) {
    asm volatile(
        "mma.sync.aligned.m16n8k8.row.col.f32.tf32.tf32.f32 "
        "{%0,%1,%2,%3}, {%4,%5,%6,%7}, {%8,%9}, {%0,%1,%2,%3};"
        : "+f"(c[0]), "+f"(c[1]), "+f"(c[2]), "+f"(c[3])
        : "r"(a[0]), "r"(a[1]), "r"(a[2]), "r"(a[3]), "r"(b[0]), "r"(b[1]));
}

// ---------------- zero everything -------------------------------------------
__global__ void zero_all_kernel() {
    int i = blockIdx.x * blockDim.x + threadIdx.x;
    int nz4 = R_TOT * D / 4;            // 6.4M float4
    if (i < nz4) ((float4*)g_z)[i] = make_float4(0.f, 0.f, 0.f, 0.f);
    if (i < R_TOT) ((float4*)g_den)[i] = make_float4(0.f, 0.f, 0.f, 0.f);
    if (i == 0) { g_wsum[0] = 0.0f; g_wsum[1] = 0.0f; }
}

// ---------------- per-node a1 = celu3(features @ attn1_w.T) -----------------
__global__ void __launch_bounds__(256) a1_kernel(
    const float* __restrict__ features, const float* __restrict__ attn1_w) {
    int warp = threadIdx.x >> 5, lane = threadIdx.x & 31;
    int node = blockIdx.x * 8 + warp;
    if (node >= N_NODES) return;
    float2 f = ((const float2*)features)[node * HC + lane];
    const float2* W1 = (const float2*)attn1_w;
    float r[4];
#pragma unroll
    for (int k = 0; k < 4; k++) {
        float2 w = W1[k * HC + lane];
        r[k] = w.x * f.x + w.y * f.y;
    }
#pragma unroll
    for (int off = 16; off; off >>= 1)
#pragma unroll
        for (int k = 0; k < 4; k++)
            r[k] += __shfl_xor_sync(0xffffffffu, r[k], off);
    if (lane == 0) {
#pragma unroll
        for (int k = 0; k < 4; k++) g_a1[node * 4 + k] = celu3f(r[k]);
    }
}

// ---------------- fused edge pass: gather+rotate+eft+logits+den+scatter -----
__global__ void __launch_bounds__(256) pass1_kernel(
    const float* __restrict__ features, const float* __restrict__ r_vec,
    const float* __restrict__ attn2, const int* __restrict__ inst_m, int m) {
    int warp = threadIdx.x >> 5, lane = threadIdx.x & 31;
    int e = blockIdx.x * 8 + warp;
    if (e >= E_EDGES) return;

    const float2* rv = (const float2*)r_vec;
    float2 ra = rv[(2 * m) * HC + lane];
    float2 rb = rv[(2 * m + 1) * HC + lane];
    float ia = rsqrtf(ra.x * ra.x + ra.y * ra.y);
    float ib = rsqrtf(rb.x * rb.x + rb.y * rb.y);
    ra.x *= ia; ra.y *= ia; rb.x *= ib; rb.y *= ib;
    float fr0x = rb.x * ra.x - rb.y * ra.y;
    float fr0y = rb.x * ra.y + rb.y * ra.x;

    const int* ip = inst_m + e * 3;
    int i0 = ip[0], i1 = ip[1], i2 = ip[2];
    const float2* F = (const float2*)features;
    float2 f0 = F[i0 * HC + lane];
    float2 f1 = F[i1 * HC + lane];
    float2 f2 = F[i2 * HC + lane];

    float mre = (f0.x * fr0x - f0.y * fr0y) + (f1.x * rb.x - f1.y * rb.y) + f2.x;
    float mim = (f0.x * fr0y + f0.y * fr0x) + (f1.x * rb.y + f1.y * rb.x) + f2.y;
    mre *= (1.0f / 3.0f); mim *= (1.0f / 3.0f);

    float se0 = celu3f(mre) * (1.0f / (1.0f + expf(-mre)));
    float se1 = celu3f(mim) * (1.0f / (1.0f + expf(-mim)));
    float ef0 = celu3f(se0), ef1 = celu3f(se1);

    // a2 = eft @ attn2.T (4 heads), full-butterfly so every lane has sums
    float r[4];
    const float2* W2 = (const float2*)attn2;
#pragma unroll
    for (int k = 0; k < 4; k++) {
        float2 w2 = W2[k * HC + lane];
        r[k] = w2.x * ef0 + w2.y * ef1;
    }
#pragma unroll
    for (int off = 16; off; off >>= 1)
#pragma unroll
        for (int k = 0; k < 4; k++)
            r[k] += __shfl_xor_sync(0xffffffffu, r[k], off);

    float4 a1v = *(const float4*)(g_a1 + (size_t)i0 * 4);
    float ex0 = expf(celu3f(a1v.x + r[0]));
    float ex1 = expf(celu3f(a1v.y + r[1]));
    float ex2 = expf(celu3f(a1v.z + r[2]));
    float ex3 = expf(celu3f(a1v.w + r[3]));

    size_t rowg = (size_t)m * N_NODES + i0;
    if (lane < 4) {
        float exv = lane == 0 ? ex0 : lane == 1 ? ex1 : lane == 2 ? ex2 : ex3;
        atomicAdd(g_den + rowg * 4 + lane, exv);
    }

    // pair-exchange so each lane holds 4 consecutive channels
    float p0 = __shfl_xor_sync(0xffffffffu, ef0, 1);
    float p1 = __shfl_xor_sync(0xffffffffu, ef1, 1);
    float v0, v1, v2, v3;
    if ((lane & 1) == 0) { v0 = ef0; v1 = ef1; v2 = p0; v3 = p1; }
    else                 { v0 = p0;  v1 = p1;  v2 = ef0; v3 = ef1; }
    int g4 = (lane >> 1) * 4;           // channel group base (0..60 step 4)
    int k0 = (lane & 1) * 2;            // heads {0,1} or {2,3}
    float exa = (lane & 1) ? ex2 : ex0;
    float exb = (lane & 1) ? ex3 : ex1;

    float* base = g_z + rowg * D;
    float* pa = base + k0 * H + g4;
    float* pb = base + (k0 + 1) * H + g4;
    asm volatile("red.global.add.v4.f32 [%0], {%1,%2,%3,%4};" ::
                 "l"(pa), "f"(exa * v0), "f"(exa * v1),
                 "f"(exa * v2), "f"(exa * v3) : "memory");
    asm volatile("red.global.add.v4.f32 [%0], {%1,%2,%3,%4};" ::
                 "l"(pb), "f"(exb * v0), "f"(exb * v1),
                 "f"(exb * v2), "f"(exb * v3) : "memory");
}

// ---------------- den -> reciprocal (guard isolated nodes) ------------------
__global__ void recip_kernel() {
    int i = blockIdx.x * blockDim.x + threadIdx.x;
    if (i < R_TOT * HEADS) {
        float d = g_den[i];
        g_den[i] = d > 0.0f ? 1.0f / d : 0.0f;
    }
}

// ---------------- MLP layer 1: t1 = celu3(fw1 @ celu3(z*inv) + fb1) ---------
// grid 148; per block: loop half (fw1 128-row panel in smem), loop row tiles.
__global__ void __launch_bounds__(256, 1) mlp_l1_kernel(
    const float* __restrict__ fw1, const float* __restrict__ fb1) {
    extern __shared__ float dsm[];
    float* Bs = dsm;                 // [128][ZST]
    float* zt = dsm + 128 * ZST;     // [TILE][ZST]
    int tid = threadIdx.x;
    int w = tid >> 5, lane = tid & 31;
    int rg = w & 1, cq = w >> 1;     // row-group (16), col-quarter (32)

    for (int half = 0; half < 2; half++) {
        __syncthreads();
        // stage fw1 half -> smem (tf32-rounded)
        for (int i = tid; i < 128 * 256; i += 256) {
            int n = i >> 8, k = i & 255;
            Bs[n * ZST + k] =
                __uint_as_float(tf32r(fw1[(size_t)(half * 128 + n) * 256 + k]));
        }
        __syncthreads();

        for (int t = blockIdx.x; t < NTILES; t += GRID_MLP) {
            // stage z tile: celu3(z * inv_den), tf32-rounded
            int head = tid >> 6;
#pragma unroll 4
            for (int r = 0; r < TILE; r++) {
                int row = t * TILE + r;
                float inv = g_den[(size_t)row * 4 + head];
                float z = g_z[(size_t)row * D + tid];
                zt[r * ZST + tid] = __uint_as_float(tf32r(celu3f(z * inv)));
            }
            __syncthreads();

            float acc[4][4];
#pragma unroll
            for (int nb = 0; nb < 4; nb++)
#pragma unroll
                for (int c = 0; c < 4; c++) acc[nb][c] = 0.0f;

            int arow = (rg * 16 + (lane >> 2)) * ZST + (lane & 3);
#pragma unroll 4
            for (int ks = 0; ks < 32; ks++) {
                int k0 = ks * 8;
                unsigned a[4];
                a[0] = __float_as_uint(zt[arow + k0]);
                a[1] = __float_as_uint(zt[arow + 8 * ZST + k0]);
                a[2] = __float_as_uint(zt[arow + k0 + 4]);
                a[3] = __float_as_uint(zt[arow + 8 * ZST + k0 + 4]);
#pragma unroll
                for (int nb = 0; nb < 4; nb++) {
                    int bn = (cq * 32 + nb * 8 + (lane >> 2)) * ZST + k0 + (lane & 3);
                    unsigned b[2];
                    b[0] = __float_as_uint(Bs[bn]);
                    b[1] = __float_as_uint(Bs[bn + 4]);
                    mma_tf32(acc[nb], a, b);
                }
            }
            __syncthreads();

            // bias + celu -> zt (local cols 0..127), then coalesced copy-out
            int rowl = rg * 16 + (lane >> 2);
#pragma unroll
            for (int nb = 0; nb < 4; nb++) {
                int n = cq * 32 + nb * 8 + 2 * (lane & 3);
                float b0f = fb1[half * 128 + n];
                float b1f = fb1[half * 128 + n + 1];
                zt[rowl * ZST + n]           = celu3f(acc[nb][0] + b0f);
                zt[rowl * ZST + n + 1]       = celu3f(acc[nb][1] + b1f);
                zt[(rowl + 8) * ZST + n]     = celu3f(acc[nb][2] + b0f);
                zt[(rowl + 8) * ZST + n + 1] = celu3f(acc[nb][3] + b1f);
            }
            __syncthreads();

            int r = tid >> 3, cb = (tid & 7) * 16;
            size_t gb = (size_t)(t * TILE + r) * D + half * 128 + cb;
#pragma unroll
            for (int i = 0; i < 4; i++) {
                float4 v = *(const float4*)&zt[r * ZST + cb + 4 * i];
                *(float4*)(g_t1 + gb + 4 * i) = v;
            }
            __syncthreads();
        }
    }
}

// ---------------- MLP layer 2 + 3: w-sums -----------------------------------
__global__ void __launch_bounds__(256, 1) mlp_l2_kernel(
    const float* __restrict__ fw2, const float* __restrict__ fb2,
    const float* __restrict__ fw3) {
    extern __shared__ float dsm[];
    float* Bs = dsm;                 // [128][ZST]
    float* zt = dsm + 128 * ZST;     // [TILE][ZST]
    int tid = threadIdx.x;
    int w = tid >> 5, lane = tid & 31;
    int rg = w & 1, cq = w >> 1;

    // stage fw2 (tf32-rounded)
    for (int i = tid; i < 128 * 256; i += 256) {
        int n = i >> 8, k = i & 255;
        Bs[n * ZST + k] = __uint_as_float(tf32r(fw2[(size_t)n * 256 + k]));
    }
    // per-lane bias / fw3 for its 8 output cols
    float fb2c[8], fw3c[8];
#pragma unroll
    for (int nb = 0; nb < 4; nb++) {
        int n = cq * 32 + nb * 8 + 2 * (lane & 3);
        fb2c[2 * nb] = fb2[n];     fb2c[2 * nb + 1] = fb2[n + 1];
        fw3c[2 * nb] = fw3[n];     fw3c[2 * nb + 1] = fw3[n + 1];
    }
    __syncthreads();

    float vsum0 = 0.0f, vsum1 = 0.0f;

    for (int t = blockIdx.x; t < NTILES; t += GRID_MLP) {
#pragma unroll 4
        for (int r = 0; r < TILE; r++) {
            float v = g_t1[(size_t)(t * TILE + r) * D + tid];
            zt[r * ZST + tid] = __uint_as_float(tf32r(v));
        }
        __syncthreads();

        float acc[4][4];
#pragma unroll
        for (int nb = 0; nb < 4; nb++)
#pragma unroll
            for (int c = 0; c < 4; c++) acc[nb][c] = 0.0f;

        int arow = (rg * 16 + (lane >> 2)) * ZST + (lane & 3);
#pragma unroll 4
        for (int ks = 0; ks < 32; ks++) {
            int k0 = ks * 8;
            unsigned a[4];
            a[0] = __float_as_uint(zt[arow + k0]);
            a[1] = __float_as_uint(zt[arow + 8 * ZST + k0]);
            a[2] = __float_as_uint(zt[arow + k0 + 4]);
            a[3] = __float_as_uint(zt[arow + 8 * ZST + k0 + 4]);
#pragma unroll
            for (int nb = 0; nb < 4; nb++) {
                int bn = (cq * 32 + nb * 8 + (lane >> 2)) * ZST + k0 + (lane & 3);
                unsigned b[2];
                b[0] = __float_as_uint(Bs[bn]);
                b[1] = __float_as_uint(Bs[bn + 4]);
                mma_tf32(acc[nb], a, b);
            }
        }

        int row_lo = t * TILE + rg * 16 + (lane >> 2);
        int row_hi = row_lo + 8;
        float clo = 0.0f, chi = 0.0f;
#pragma unroll
        for (int nb = 0; nb < 4; nb++) {
            clo += fw3c[2 * nb]     * celu3f(acc[nb][0] + fb2c[2 * nb]);
            clo += fw3c[2 * nb + 1] * celu3f(acc[nb][1] + fb2c[2 * nb + 1]);
            chi += fw3c[2 * nb]     * celu3f(acc[nb][2] + fb2c[2 * nb]);
            chi += fw3c[2 * nb + 1] * celu3f(acc[nb][3] + fb2c[2 * nb + 1]);
        }
        if (row_lo < N_NODES) vsum0 += clo; else vsum1 += clo;
        if (row_hi < N_NODES) vsum0 += chi; else vsum1 += chi;
        __syncthreads();
    }

#pragma unroll
    for (int off = 16; off; off >>= 1) {
        vsum0 += __shfl_xor_sync(0xffffffffu, vsum0, off);
        vsum1 += __shfl_xor_sync(0xffffffffu, vsum1, off);
    }
    if (lane == 0) {
        atomicAdd(&g_wsum[0], vsum0);
        atomicAdd(&g_wsum[1], vsum1);
    }
}

__global__ void beta_kernel() {
    float w0 = g_wsum[0] * (1.0f / (float)N_NODES);
    float w1 = g_wsum[1] * (1.0f / (float)N_NODES);
    float mx = fmaxf(w0, w1);
    float e0 = expf(w0 - mx), e1 = expf(w1 - mx);
    float inv = 1.0f / (e0 + e1);
    g_beta[0] = e0 * inv;
    g_beta[1] = e1 * inv;
}

__global__ void combine_kernel(float* __restrict__ out) {
    int i = blockIdx.x * blockDim.x + threadIdx.x;
    int n4 = N_NODES * D / 4;
    if (i < n4) {
        int f = i * 4;
        int node = f >> 8;
        int head = (f & 255) >> 6;
        float inv0 = g_den[(size_t)node * 4 + head];
        float inv1 = g_den[(size_t)(N_NODES + node) * 4 + head];
        float b0 = g_beta[0], b1 = g_beta[1];
        float4 a = ((const float4*)g_z)[i];
        float4 c = ((const float4*)(g_z + (size_t)N_NODES * D))[i];
        float4 o;
        o.x = b0 * celu3f(a.x * inv0) + b1 * celu3f(c.x * inv1);
        o.y = b0 * celu3f(a.y * inv0) + b1 * celu3f(c.y * inv1);
        o.z = b0 * celu3f(a.z * inv0) + b1 * celu3f(c.z * inv1);
        o.w = b0 * celu3f(a.w * inv0) + b1 * celu3f(c.w * inv1);
        ((float4*)out)[i] = o;
    }
}

extern "C" void kernel_launch(void* const* d_in, const int* in_sizes, int n_in,
                              void* d_out, int out_size) {
    const float* features = (const float*)d_in[0];
    const float* r_vec    = (const float*)d_in[1];
    const float* attn1_w  = (const float*)d_in[2];
    const float* attn2    = (const float*)d_in[3];
    const float* fw1      = (const float*)d_in[4];
    const float* fb1      = (const float*)d_in[5];
    const float* fw2      = (const float*)d_in[6];
    const float* fb2      = (const float*)d_in[7];
    const float* fw3      = (const float*)d_in[8];
    const int*   inst     = (const int*)d_in[9];
    float* out = (float*)d_out;

    cudaFuncSetAttribute(mlp_l1_kernel,
                         cudaFuncAttributeMaxDynamicSharedMemorySize, SMEM_MLP);
    cudaFuncSetAttribute(mlp_l2_kernel,
                         cudaFuncAttributeMaxDynamicSharedMemorySize, SMEM_MLP);

    zero_all_kernel<<<(R_TOT * D / 4 + 255) / 256, 256>>>();            // 1
    a1_kernel<<<(N_NODES + 7) / 8, 256>>>(features, attn1_w);           // 2
    for (int m = 0; m < M_PATHS; m++) {                                 // 3,4
        const int* inst_m = inst + (size_t)m * E_EDGES * P_LEN;
        pass1_kernel<<<E_EDGES / 8, 256>>>(features, r_vec, attn2, inst_m, m);
    }
    recip_kernel<<<(R_TOT * HEADS + 255) / 256, 256>>>();               // 5
    mlp_l1_kernel<<<GRID_MLP, 256, SMEM_MLP>>>(fw1, fb1);               // 6 (ncu)
    mlp_l2_kernel<<<GRID_MLP, 256, SMEM_MLP>>>(fw2, fb2, fw3);          // 7
    beta_kernel<<<1, 1>>>();                                            // 8
    combine_kernel<<<(N_NODES * D / 4 + 255) / 256, 256>>>(out);        // 9
}